// round 16
// baseline (speedup 1.0000x reference)
#include <cuda_runtime.h>
#include <cstdint>

// Problem constants
#define NB        32
#define D         768
#define EMBD      768
#define NPOS      196        // 14*14 patches per image
#define ROWS_TOTAL 6272      // NB * NPOS
#define NC0       512
#define NC1       2048
#define NC2       8192
#define OUTSLICE  4816896    // 32*768*196 == 32*3*224*224

// GEMM tiling (wide kernel)
#define BM 128
#define BN 128
#define BK 16
#define BDS 284    // duplicated-B smem row stride (words); W(c)=2c+4*((2c)>>5), max 282
// narrow kernel (stage 0)
#define BN64 64

// ---------------- scratch (static device memory; no allocation) ----------------
__device__ float g_X [ROWS_TOTAL * D];
__device__ float g_D1[ROWS_TOTAL * D];
__device__ float g_D2[ROWS_TOTAL * D];
__device__ float g_norms[NC0 + NC1 + NC2];
__device__ unsigned long long g_best[ROWS_TOTAL];
__device__ int g_cls0[ROWS_TOTAL];
__device__ int g_cls1[ROWS_TOTAL];
__device__ int g_cls2[ROWS_TOTAL];

// ---------------- helpers ----------------
__device__ __forceinline__ unsigned long long pk2(float v) {
    unsigned long long r;
    asm("mov.b64 %0, {%1, %1};" : "=l"(r) : "f"(v));
    return r;
}
__device__ __forceinline__ void ffma2(unsigned long long& d, unsigned long long a, unsigned long long b) {
    asm("fma.rn.f32x2 %0, %1, %2, %0;" : "+l"(d) : "l"(a), "l"(b));
}
__device__ __forceinline__ void unpk(unsigned long long v, float& lo, float& hi) {
    asm("mov.b64 {%0, %1}, %2;" : "=f"(lo), "=f"(hi) : "l"(v));
}
// order-preserving float -> uint key (ascending)
__device__ __forceinline__ unsigned fkey(float f) {
    unsigned u = __float_as_uint(f);
    return (u & 0x80000000u) ? ~u : (u | 0x80000000u);
}

// ---------------- patchify: data[b,3,224,224] -> X[row, f] ----------------
__global__ void patchify_kernel(const float* __restrict__ data, float* __restrict__ X) {
    int row = blockIdx.x;
    int b  = row / NPOS;
    int p  = row - b * NPOS;
    int ph = p / 14;
    int pw = p - ph * 14;
    const float* src = data + (size_t)b * 3 * 224 * 224;
    float* dst = X + (size_t)row * D;
    for (int f = threadIdx.x; f < D; f += blockDim.x) {
        int c = f >> 8;
        int i = (f >> 4) & 15;
        int j = f & 15;
        dst[f] = src[((size_t)c * 224 + (ph * 16 + i)) * 224 + (pw * 16 + j)];
    }
}

// ---------------- ||c||^2 per center ----------------
__global__ void norms_kernel(const float* __restrict__ C, float* __restrict__ out) {
    int k = blockIdx.x;
    const float* row = C + (size_t)k * D;
    float s = 0.f;
    for (int i = threadIdx.x; i < D; i += 256) {
        float v = row[i];
        s += v * v;
    }
    #pragma unroll
    for (int o = 16; o; o >>= 1) s += __shfl_xor_sync(0xffffffffu, s, o);
    __shared__ float red[8];
    if ((threadIdx.x & 31) == 0) red[threadIdx.x >> 5] = s;
    __syncthreads();
    if (threadIdx.x == 0) {
        float t = 0.f;
        #pragma unroll
        for (int w = 0; w < 8; w++) t += red[w];
        out[k] = t;
    }
}

// ---------------- init best to +inf key ----------------
__global__ void init_best_kernel(unsigned long long* __restrict__ best) {
    int i = blockIdx.x * 256 + threadIdx.x;
    if (i < ROWS_TOTAL) best[i] = ~0ull;
}

// ---------------- fused GEMM + argmin (128x128 tile, B pre-duplicated in smem) ----------------
// scores[r, n] = norms[n] - 2 * dot(X[r], C[n]); atomicMin of packed (key, idx)
__global__ __launch_bounds__(256, 2) void score_kernel(
    const float* __restrict__ X, const float* __restrict__ C,
    const float* __restrict__ norms, unsigned long long* __restrict__ best)
{
    __shared__ __align__(16) float As[BK][BM];
    __shared__ __align__(16) float Bs[BK][BDS];   // duplicated pairs: word W(c)=2c+4*((2c)>>5)
    __shared__ unsigned long long red[BM];

    const int tid = threadIdx.x;
    const int tx = tid & 15;             // 8 N-cols each: n = tx*8 .. tx*8+7
    const int ty = tid >> 4;             // 8 M-rows each: m = ty*8 .. ty*8+7
    const int rowTile = blockIdx.x * BM;
    const int colTile = blockIdx.y * BN;

    // global->smem load mapping (float4 per thread)
    const int ar0  = tid >> 2;           // 0..63
    const int ak   = (tid & 3) << 2;     // k offset {0,4,8,12}
    const int aswz = (tid & 3) << 3;     // A XOR swizzle {0,8,16,24}

    // B duplicated store word offsets for cols ar0 and ar0+64
    const int v0  = 2 * ar0;
    const int bw0 = v0 + 4 * (v0 >> 5);
    const int v1  = 2 * (ar0 + 64);
    const int bw1 = v1 + 4 * (v1 >> 5);
    // B read base word (4 consecutive LDS.128 cover this thread's 8 dup-pairs)
    const int rwb = 16 * tx + 4 * (tx >> 1);

    unsigned long long acc[4][8];
    #pragma unroll
    for (int i = 0; i < 4; i++)
        #pragma unroll
        for (int j = 0; j < 8; j++) acc[i][j] = 0ull;

    const float* Xbase  = X + (size_t)(rowTile + ar0) * D + ak;
    const float* Xbase2 = Xbase + (size_t)64 * D;
    const float* Cb0    = C + (size_t)(colTile + ar0) * D + ak;
    const float* Cb1    = Cb0 + (size_t)64 * D;

    float4 pa0 = *(const float4*)(Xbase);
    float4 pa1 = *(const float4*)(Xbase2);
    float4 pb0 = *(const float4*)(Cb0);
    float4 pb1 = *(const float4*)(Cb1);

    for (int kt = 0; kt < D; kt += BK) {
        // store current tile to smem (A as R7; B duplicated as (v,v) pairs)
        {
            int ca  = ar0 ^ aswz;
            As[ak + 0][ca] = pa0.x; As[ak + 1][ca] = pa0.y;
            As[ak + 2][ca] = pa0.z; As[ak + 3][ca] = pa0.w;
            int ca2 = (ar0 + 64) ^ aswz;
            As[ak + 0][ca2] = pa1.x; As[ak + 1][ca2] = pa1.y;
            As[ak + 2][ca2] = pa1.z; As[ak + 3][ca2] = pa1.w;
            *(float2*)&Bs[ak + 0][bw0] = make_float2(pb0.x, pb0.x);
            *(float2*)&Bs[ak + 1][bw0] = make_float2(pb0.y, pb0.y);
            *(float2*)&Bs[ak + 2][bw0] = make_float2(pb0.z, pb0.z);
            *(float2*)&Bs[ak + 3][bw0] = make_float2(pb0.w, pb0.w);
            *(float2*)&Bs[ak + 0][bw1] = make_float2(pb1.x, pb1.x);
            *(float2*)&Bs[ak + 1][bw1] = make_float2(pb1.y, pb1.y);
            *(float2*)&Bs[ak + 2][bw1] = make_float2(pb1.z, pb1.z);
            *(float2*)&Bs[ak + 3][bw1] = make_float2(pb1.w, pb1.w);
        }
        __syncthreads();

        // prefetch next tile
        if (kt + BK < D) {
            pa0 = *(const float4*)(Xbase  + kt + BK);
            pa1 = *(const float4*)(Xbase2 + kt + BK);
            pb0 = *(const float4*)(Cb0 + kt + BK);
            pb1 = *(const float4*)(Cb1 + kt + BK);
        }

        // compute: 4 M-pairs x 8 N per kk; no pk2 MOVs — b pairs come straight from smem
        #pragma unroll
        for (int kk = 0; kk < BK; kk++) {
            const int offs = ((kk >> 2) & 3) << 3;
            const int sa = (ty * 8) ^ offs;
            ulonglong2 a01 = *(const ulonglong2*)&As[kk][sa];
            ulonglong2 a23 = *(const ulonglong2*)&As[kk][sa + 4];
            ulonglong2 b01 = *(const ulonglong2*)&Bs[kk][rwb];
            ulonglong2 b23 = *(const ulonglong2*)&Bs[kk][rwb + 4];
            ulonglong2 b45 = *(const ulonglong2*)&Bs[kk][rwb + 8];
            ulonglong2 b67 = *(const ulonglong2*)&Bs[kk][rwb + 12];
            unsigned long long b[8];
            b[0] = b01.x; b[1] = b01.y; b[2] = b23.x; b[3] = b23.y;
            b[4] = b45.x; b[5] = b45.y; b[6] = b67.x; b[7] = b67.y;
            unsigned long long A0 = a01.x, A1 = a01.y, A2v = a23.x, A3 = a23.y;
            #pragma unroll
            for (int j = 0; j < 8; j++) {
                ffma2(acc[0][j], A0, b[j]);
                ffma2(acc[1][j], A1, b[j]);
                ffma2(acc[2][j], A2v, b[j]);
                ffma2(acc[3][j], A3, b[j]);
            }
        }
        __syncthreads();
    }

    // per-thread argmin over its 8 columns, then block/global reduction
    float nrm[8];
    #pragma unroll
    for (int j = 0; j < 8; j++) nrm[j] = norms[colTile + tx * 8 + j];

    if (tid < BM) red[tid] = ~0ull;
    __syncthreads();

    #pragma unroll
    for (int i = 0; i < 4; i++) {
        float lo[8], hi[8];
        #pragma unroll
        for (int j = 0; j < 8; j++) unpk(acc[i][j], lo[j], hi[j]);

        // row = ty*8 + 2i (lo lane)
        {
            float bs = nrm[0] - 2.f * lo[0];
            int bn = 0;
            #pragma unroll
            for (int j = 1; j < 8; j++) {
                float s = nrm[j] - 2.f * lo[j];
                if (s < bs) { bs = s; bn = j; }
            }
            unsigned long long key =
                ((unsigned long long)fkey(bs) << 32) | (unsigned)(colTile + tx * 8 + bn);
            atomicMin(&red[ty * 8 + 2 * i], key);
        }
        // row = ty*8 + 2i + 1 (hi lane)
        {
            float bs = nrm[0] - 2.f * hi[0];
            int bn = 0;
            #pragma unroll
            for (int j = 1; j < 8; j++) {
                float s = nrm[j] - 2.f * hi[j];
                if (s < bs) { bs = s; bn = j; }
            }
            unsigned long long key =
                ((unsigned long long)fkey(bs) << 32) | (unsigned)(colTile + tx * 8 + bn);
            atomicMin(&red[ty * 8 + 2 * i + 1], key);
        }
    }
    __syncthreads();
    if (tid < BM) atomicMin(&best[rowTile + tid], red[tid]);
}

// ---------------- fused GEMM + argmin (128x64 tile) — R4 kernel, for stage 0 ----------------
__global__ __launch_bounds__(256) void score64_kernel(
    const float* __restrict__ X, const float* __restrict__ C,
    const float* __restrict__ norms, unsigned long long* __restrict__ best)
{
    __shared__ float As[BK][BM];
    __shared__ float Bs[BK][BN64];
    __shared__ unsigned long long red[BM];

    const int tid = threadIdx.x;
    const int tx = tid & 15;
    const int ty = tid >> 4;
    const int rowTile = blockIdx.x * BM;
    const int colTile = blockIdx.y * BN64;

    const int ar0  = tid >> 2;             // 0..63
    const int ak   = (tid & 3) << 2;       // {0,4,8,12}
    const int aswz = (tid & 3) << 3;       // {0,8,16,24}

    unsigned long long acc[4][4];
    #pragma unroll
    for (int i = 0; i < 4; i++)
        #pragma unroll
        for (int j = 0; j < 4; j++) acc[i][j] = 0ull;

    const float* Xbase  = X + (size_t)(rowTile + ar0) * D + ak;
    const float* Xbase2 = Xbase + (size_t)64 * D;
    const float* Cbase  = C + (size_t)(colTile + ar0) * D + ak;

    float4 pa0 = *(const float4*)(Xbase);
    float4 pa1 = *(const float4*)(Xbase2);
    float4 pb  = *(const float4*)(Cbase);

    for (int kt = 0; kt < D; kt += BK) {
        {
            int ca  = ar0 ^ aswz;
            As[ak + 0][ca] = pa0.x; As[ak + 1][ca] = pa0.y;
            As[ak + 2][ca] = pa0.z; As[ak + 3][ca] = pa0.w;
            int ca2 = (ar0 + 64) ^ aswz;
            As[ak + 0][ca2] = pa1.x; As[ak + 1][ca2] = pa1.y;
            As[ak + 2][ca2] = pa1.z; As[ak + 3][ca2] = pa1.w;
            int cb  = ar0 ^ aswz;
            Bs[ak + 0][cb] = pb.x; Bs[ak + 1][cb] = pb.y;
            Bs[ak + 2][cb] = pb.z; Bs[ak + 3][cb] = pb.w;
        }
        __syncthreads();

        if (kt + BK < D) {
            pa0 = *(const float4*)(Xbase  + kt + BK);
            pa1 = *(const float4*)(Xbase2 + kt + BK);
            pb  = *(const float4*)(Cbase  + kt + BK);
        }

        #pragma unroll
        for (int kk = 0; kk < BK; kk++) {
            const int offs = ((kk >> 2) & 3) << 3;
            const int sa = (ty * 8) ^ offs;
            const int sb = (tx * 4) ^ offs;
            ulonglong2 a01 = *(const ulonglong2*)&As[kk][sa];
            ulonglong2 a23 = *(const ulonglong2*)&As[kk][sa + 4];
            float4 bv = *(const float4*)&Bs[kk][sb];
            unsigned long long b0 = pk2(bv.x), b1 = pk2(bv.y),
                               b2 = pk2(bv.z), b3 = pk2(bv.w);
            unsigned long long A0 = a01.x, A1 = a01.y, A2v = a23.x, A3 = a23.y;
            ffma2(acc[0][0], A0, b0); ffma2(acc[0][1], A0, b1);
            ffma2(acc[0][2], A0, b2); ffma2(acc[0][3], A0, b3);
            ffma2(acc[1][0], A1, b0); ffma2(acc[1][1], A1, b1);
            ffma2(acc[1][2], A1, b2); ffma2(acc[1][3], A1, b3);
            ffma2(acc[2][0], A2v, b0); ffma2(acc[2][1], A2v, b1);
            ffma2(acc[2][2], A2v, b2); ffma2(acc[2][3], A2v, b3);
            ffma2(acc[3][0], A3, b0); ffma2(acc[3][1], A3, b1);
            ffma2(acc[3][2], A3, b2); ffma2(acc[3][3], A3, b3);
        }
        __syncthreads();
    }

    float nrm[4];
    #pragma unroll
    for (int j = 0; j < 4; j++) nrm[j] = norms[colTile + tx * 4 + j];

    if (tid < BM) red[tid] = ~0ull;
    __syncthreads();

    #pragma unroll
    for (int i = 0; i < 4; i++) {
        float lo[4], hi[4];
        #pragma unroll
        for (int j = 0; j < 4; j++) unpk(acc[i][j], lo[j], hi[j]);
        {
            float bs = nrm[0] - 2.f * lo[0];
            int bn = 0;
            #pragma unroll
            for (int j = 1; j < 4; j++) {
                float s = nrm[j] - 2.f * lo[j];
                if (s < bs) { bs = s; bn = j; }
            }
            unsigned long long key =
                ((unsigned long long)fkey(bs) << 32) | (unsigned)(colTile + tx * 4 + bn);
            atomicMin(&red[ty * 8 + 2 * i], key);
        }
        {
            float bs = nrm[0] - 2.f * hi[0];
            int bn = 0;
            #pragma unroll
            for (int j = 1; j < 4; j++) {
                float s = nrm[j] - 2.f * hi[j];
                if (s < bs) { bs = s; bn = j; }
            }
            unsigned long long key =
                ((unsigned long long)fkey(bs) << 32) | (unsigned)(colTile + tx * 4 + bn);
            atomicMin(&red[ty * 8 + 2 * i + 1], key);
        }
    }
    __syncthreads();
    if (tid < BM) atomicMin(&best[rowTile + tid], red[tid]);
}

// ---------------- gather: diff = prev - C[cls]; record cls ----------------
__global__ void gather_kernel(const float* __restrict__ prev, const float* __restrict__ C,
                              const unsigned long long* __restrict__ best,
                              float* __restrict__ outd, int* __restrict__ cls)
{
    int row = blockIdx.x;
    int k = (int)(best[row] & 0xffffffffull);
    if (threadIdx.x == 0) cls[row] = k;
    const float4* pr = (const float4*)(prev + (size_t)row * D);
    const float4* cr = (const float4*)(C + (size_t)k * D);
    float4* orow = (float4*)(outd + (size_t)row * D);
    for (int f = threadIdx.x; f < D / 4; f += blockDim.x) {
        float4 a = pr[f];
        float4 b = cr[f];
        orow[f] = make_float4(a.x - b.x, a.y - b.y, a.z - b.z, a.w - b.w);
    }
}

// ---------------- embed ----------------
__global__ void embed_kernel(const float* __restrict__ e0, const float* __restrict__ e1,
                             const float* __restrict__ e2,
                             const int* __restrict__ cls0, const int* __restrict__ cls1,
                             const int* __restrict__ cls2, float* __restrict__ out)
{
    int b = blockIdx.x;
    int ebase = blockIdx.y * 8;
    __shared__ int s0[NPOS], s1[NPOS], s2[NPOS];
    for (int p = threadIdx.x; p < NPOS; p += blockDim.x) {
        int r = b * NPOS + p;
        s0[p] = cls0[r]; s1[p] = cls1[r]; s2[p] = cls2[r];
    }
    __syncthreads();
    for (int idx = threadIdx.x; idx < 8 * NPOS; idx += blockDim.x) {
        int e = ebase + idx / NPOS;
        int p = idx - (idx / NPOS) * NPOS;
        out[((size_t)b * EMBD + e) * NPOS + p] =
            e0[(size_t)s0[p] * EMBD + e] +
            e1[(size_t)s1[p] * EMBD + e] +
            e2[(size_t)s2[p] * EMBD + e];
    }
}

// ---------------- img_sum ----------------
__global__ void img_kernel(const float* __restrict__ X, const float* __restrict__ Df,
                           float* __restrict__ out)
{
    int b = blockIdx.x, c = blockIdx.y, h = blockIdx.z;
    int w = threadIdx.x;
    int row = b * NPOS + (h >> 4) * 14 + (w >> 4);
    int f = (c << 8) + ((h & 15) << 4) + (w & 15);
    size_t o = (((size_t)b * 3 + c) * 224 + h) * 224 + w;
    size_t s = (size_t)row * D + f;
    out[o] = X[s] - Df[s];
}

// ---------------- diff_out ----------------
__global__ void diffout_kernel(const float* __restrict__ Df, float* __restrict__ out)
{
    int b = blockIdx.x;
    int fbase = blockIdx.y * 8;
    for (int idx = threadIdx.x; idx < 8 * NPOS; idx += blockDim.x) {
        int f = fbase + idx / NPOS;
        int p = idx - (idx / NPOS) * NPOS;
        out[((size_t)b * D + f) * NPOS + p] = Df[((size_t)(b * NPOS + p)) * D + f];
    }
}

// ---------------- launch ----------------
extern "C" void kernel_launch(void* const* d_in, const int* in_sizes, int n_in,
                              void* d_out, int out_size)
{
    const float* data = (const float*)d_in[0];
    const float* c0 = (const float*)d_in[1];
    const float* c1 = (const float*)d_in[2];
    const float* c2 = (const float*)d_in[3];
    const float* e0 = (const float*)d_in[4];
    const float* e1 = (const float*)d_in[5];
    const float* e2 = (const float*)d_in[6];
    float* out = (float*)d_out;

    void *pX, *pD1, *pD2, *pN, *pB, *pC0, *pC1, *pC2;
    cudaGetSymbolAddress(&pX, g_X);
    cudaGetSymbolAddress(&pD1, g_D1);
    cudaGetSymbolAddress(&pD2, g_D2);
    cudaGetSymbolAddress(&pN, g_norms);
    cudaGetSymbolAddress(&pB, g_best);
    cudaGetSymbolAddress(&pC0, g_cls0);
    cudaGetSymbolAddress(&pC1, g_cls1);
    cudaGetSymbolAddress(&pC2, g_cls2);
    float* X  = (float*)pX;
    float* D1 = (float*)pD1;
    float* D2 = (float*)pD2;
    float* nrm = (float*)pN;
    unsigned long long* best = (unsigned long long*)pB;
    int* cls0 = (int*)pC0;
    int* cls1 = (int*)pC1;
    int* cls2 = (int*)pC2;

    patchify_kernel<<<ROWS_TOTAL, 256>>>(data, X);
    norms_kernel<<<NC0, 256>>>(c0, nrm);
    norms_kernel<<<NC1, 256>>>(c1, nrm + NC0);
    norms_kernel<<<NC2, 256>>>(c2, nrm + NC0 + NC1);

    // stage 0 (narrow tile: 392 CTAs -> better per-SM balance)
    init_best_kernel<<<(ROWS_TOTAL + 255) / 256, 256>>>(best);
    score64_kernel<<<dim3(ROWS_TOTAL / BM, NC0 / BN64), 256>>>(X, c0, nrm, best);
    gather_kernel<<<ROWS_TOTAL, 192>>>(X, c0, best, D1, cls0);

    // stage 1
    init_best_kernel<<<(ROWS_TOTAL + 255) / 256, 256>>>(best);
    score_kernel<<<dim3(ROWS_TOTAL / BM, NC1 / BN), 256>>>(D1, c1, nrm + NC0, best);
    gather_kernel<<<ROWS_TOTAL, 192>>>(D1, c1, best, D2, cls1);

    // stage 2
    init_best_kernel<<<(ROWS_TOTAL + 255) / 256, 256>>>(best);
    score_kernel<<<dim3(ROWS_TOTAL / BM, NC2 / BN), 256>>>(D2, c2, nrm + NC0 + NC1, best);
    gather_kernel<<<ROWS_TOTAL, 192>>>(D2, c2, best, D1, cls2);

    // outputs: [embed | img_sum | diff_out]
    embed_kernel<<<dim3(NB, EMBD / 8), 256>>>(e0, e1, e2, cls0, cls1, cls2, out);
    img_kernel<<<dim3(NB, 3, 224), 224>>>(X, D1, out + OUTSLICE);
    diffout_kernel<<<dim3(NB, D / 8), 256>>>(D1, out + 2 * OUTSLICE);
}

// round 17
// speedup vs baseline: 1.3217x; 1.3217x over previous
#include <cuda_runtime.h>
#include <cstdint>

// Problem constants
#define NB        32
#define D         768
#define EMBD      768
#define NPOS      196        // 14*14 patches per image
#define ROWS_TOTAL 6272      // NB * NPOS
#define NC0       512
#define NC1       2048
#define NC2       8192
#define OUTSLICE  4816896    // 32*768*196 == 32*3*224*224

// GEMM tiling (wide kernel)
#define BM 128
#define BN 128
#define BK 16
#define BROW 140   // padded B smem row stride (words); 140 % 32 == 12
// narrow kernel (stage 0)
#define BN64 64

// ---------------- scratch (static device memory; no allocation) ----------------
__device__ float g_X [ROWS_TOTAL * D];
__device__ float g_D1[ROWS_TOTAL * D];
__device__ float g_D2[ROWS_TOTAL * D];
__device__ float g_norms[NC0 + NC1 + NC2];
__device__ unsigned long long g_best[ROWS_TOTAL];
__device__ int g_cls0[ROWS_TOTAL];
__device__ int g_cls1[ROWS_TOTAL];
__device__ int g_cls2[ROWS_TOTAL];

// ---------------- helpers ----------------
__device__ __forceinline__ unsigned long long pk2(float v) {
    unsigned long long r;
    asm("mov.b64 %0, {%1, %1};" : "=l"(r) : "f"(v));
    return r;
}
__device__ __forceinline__ void ffma2(unsigned long long& d, unsigned long long a, unsigned long long b) {
    asm("fma.rn.f32x2 %0, %1, %2, %0;" : "+l"(d) : "l"(a), "l"(b));
}
__device__ __forceinline__ void unpk(unsigned long long v, float& lo, float& hi) {
    asm("mov.b64 {%0, %1}, %2;" : "=f"(lo), "=f"(hi) : "l"(v));
}
// order-preserving float -> uint key (ascending)
__device__ __forceinline__ unsigned fkey(float f) {
    unsigned u = __float_as_uint(f);
    return (u & 0x80000000u) ? ~u : (u | 0x80000000u);
}

// ---------------- patchify: data[b,3,224,224] -> X[row, f] ----------------
__global__ void patchify_kernel(const float* __restrict__ data, float* __restrict__ X) {
    int row = blockIdx.x;
    int b  = row / NPOS;
    int p  = row - b * NPOS;
    int ph = p / 14;
    int pw = p - ph * 14;
    const float* src = data + (size_t)b * 3 * 224 * 224;
    float* dst = X + (size_t)row * D;
    for (int f = threadIdx.x; f < D; f += blockDim.x) {
        int c = f >> 8;
        int i = (f >> 4) & 15;
        int j = f & 15;
        dst[f] = src[((size_t)c * 224 + (ph * 16 + i)) * 224 + (pw * 16 + j)];
    }
}

// ---------------- ||c||^2 per center ----------------
__global__ void norms_kernel(const float* __restrict__ C, float* __restrict__ out) {
    int k = blockIdx.x;
    const float* row = C + (size_t)k * D;
    float s = 0.f;
    for (int i = threadIdx.x; i < D; i += 256) {
        float v = row[i];
        s += v * v;
    }
    #pragma unroll
    for (int o = 16; o; o >>= 1) s += __shfl_xor_sync(0xffffffffu, s, o);
    __shared__ float red[8];
    if ((threadIdx.x & 31) == 0) red[threadIdx.x >> 5] = s;
    __syncthreads();
    if (threadIdx.x == 0) {
        float t = 0.f;
        #pragma unroll
        for (int w = 0; w < 8; w++) t += red[w];
        out[k] = t;
    }
}

// ---------------- init best to +inf key ----------------
__global__ void init_best_kernel(unsigned long long* __restrict__ best) {
    int i = blockIdx.x * 256 + threadIdx.x;
    if (i < ROWS_TOTAL) best[i] = ~0ull;
}

// ---------------- fused GEMM + argmin (128x128 tile) — R7 winner, verbatim ----------------
__global__ __launch_bounds__(256, 2) void score_kernel(
    const float* __restrict__ X, const float* __restrict__ C,
    const float* __restrict__ norms, unsigned long long* __restrict__ best)
{
    __shared__ __align__(16) float As[BK][BM];
    __shared__ __align__(16) float Bs[BK][BROW];
    __shared__ unsigned long long red[BM];

    const int tid = threadIdx.x;
    const int tx = tid & 15;             // 8 N-cols each
    const int ty = tid >> 4;             // 8 M-rows each
    const int rowTile = blockIdx.x * BM;
    const int colTile = blockIdx.y * BN;

    const int ar0  = tid >> 2;           // 0..63
    const int ak   = (tid & 3) << 2;     // k offset {0,4,8,12}
    const int aswz = (tid & 3) << 3;     // A XOR swizzle {0,8,16,24}

    const int bw0 = ar0 + ((ar0 >> 5) << 2);
    const int bw1 = (ar0 + 64) + (((ar0 + 64) >> 5) << 2);
    const int rb0 = tx * 8;
    const int rb1 = tx * 8 + 4;
    const int rw0 = rb0 + ((rb0 >> 5) << 2);
    const int rw1 = rb1 + ((rb1 >> 5) << 2);

    unsigned long long acc[4][8];
    #pragma unroll
    for (int i = 0; i < 4; i++)
        #pragma unroll
        for (int j = 0; j < 8; j++) acc[i][j] = 0ull;

    const float* Xbase  = X + (size_t)(rowTile + ar0) * D + ak;
    const float* Xbase2 = Xbase + (size_t)64 * D;
    const float* Cb0    = C + (size_t)(colTile + ar0) * D + ak;
    const float* Cb1    = Cb0 + (size_t)64 * D;

    float4 pa0 = *(const float4*)(Xbase);
    float4 pa1 = *(const float4*)(Xbase2);
    float4 pb0 = *(const float4*)(Cb0);
    float4 pb1 = *(const float4*)(Cb1);

    for (int kt = 0; kt < D; kt += BK) {
        {
            int ca  = ar0 ^ aswz;
            As[ak + 0][ca] = pa0.x; As[ak + 1][ca] = pa0.y;
            As[ak + 2][ca] = pa0.z; As[ak + 3][ca] = pa0.w;
            int ca2 = (ar0 + 64) ^ aswz;
            As[ak + 0][ca2] = pa1.x; As[ak + 1][ca2] = pa1.y;
            As[ak + 2][ca2] = pa1.z; As[ak + 3][ca2] = pa1.w;
            Bs[ak + 0][bw0] = pb0.x; Bs[ak + 1][bw0] = pb0.y;
            Bs[ak + 2][bw0] = pb0.z; Bs[ak + 3][bw0] = pb0.w;
            Bs[ak + 0][bw1] = pb1.x; Bs[ak + 1][bw1] = pb1.y;
            Bs[ak + 2][bw1] = pb1.z; Bs[ak + 3][bw1] = pb1.w;
        }
        __syncthreads();

        if (kt + BK < D) {
            pa0 = *(const float4*)(Xbase  + kt + BK);
            pa1 = *(const float4*)(Xbase2 + kt + BK);
            pb0 = *(const float4*)(Cb0 + kt + BK);
            pb1 = *(const float4*)(Cb1 + kt + BK);
        }

        #pragma unroll
        for (int kk = 0; kk < BK; kk++) {
            const int offs = ((kk >> 2) & 3) << 3;
            const int sa = (ty * 8) ^ offs;
            ulonglong2 a01 = *(const ulonglong2*)&As[kk][sa];
            ulonglong2 a23 = *(const ulonglong2*)&As[kk][sa + 4];
            float4 bv0 = *(const float4*)&Bs[kk][rw0];
            float4 bv1 = *(const float4*)&Bs[kk][rw1];
            unsigned long long b[8];
            b[0] = pk2(bv0.x); b[1] = pk2(bv0.y); b[2] = pk2(bv0.z); b[3] = pk2(bv0.w);
            b[4] = pk2(bv1.x); b[5] = pk2(bv1.y); b[6] = pk2(bv1.z); b[7] = pk2(bv1.w);
            unsigned long long A0 = a01.x, A1 = a01.y, A2v = a23.x, A3 = a23.y;
            #pragma unroll
            for (int j = 0; j < 8; j++) {
                ffma2(acc[0][j], A0, b[j]);
                ffma2(acc[1][j], A1, b[j]);
                ffma2(acc[2][j], A2v, b[j]);
                ffma2(acc[3][j], A3, b[j]);
            }
        }
        __syncthreads();
    }

    float nrm[8];
    #pragma unroll
    for (int j = 0; j < 8; j++) nrm[j] = norms[colTile + tx * 8 + j];

    if (tid < BM) red[tid] = ~0ull;
    __syncthreads();

    #pragma unroll
    for (int i = 0; i < 4; i++) {
        float lo[8], hi[8];
        #pragma unroll
        for (int j = 0; j < 8; j++) unpk(acc[i][j], lo[j], hi[j]);
        {
            float bs = nrm[0] - 2.f * lo[0];
            int bn = 0;
            #pragma unroll
            for (int j = 1; j < 8; j++) {
                float s = nrm[j] - 2.f * lo[j];
                if (s < bs) { bs = s; bn = j; }
            }
            unsigned long long key =
                ((unsigned long long)fkey(bs) << 32) | (unsigned)(colTile + tx * 8 + bn);
            atomicMin(&red[ty * 8 + 2 * i], key);
        }
        {
            float bs = nrm[0] - 2.f * hi[0];
            int bn = 0;
            #pragma unroll
            for (int j = 1; j < 8; j++) {
                float s = nrm[j] - 2.f * hi[j];
                if (s < bs) { bs = s; bn = j; }
            }
            unsigned long long key =
                ((unsigned long long)fkey(bs) << 32) | (unsigned)(colTile + tx * 8 + bn);
            atomicMin(&red[ty * 8 + 2 * i + 1], key);
        }
    }
    __syncthreads();
    if (tid < BM) atomicMin(&best[rowTile + tid], red[tid]);
}

// ---------------- fused GEMM + argmin (128x64 tile) — R4 kernel, for stage 0 ----------------
__global__ __launch_bounds__(256) void score64_kernel(
    const float* __restrict__ X, const float* __restrict__ C,
    const float* __restrict__ norms, unsigned long long* __restrict__ best)
{
    __shared__ float As[BK][BM];
    __shared__ float Bs[BK][BN64];
    __shared__ unsigned long long red[BM];

    const int tid = threadIdx.x;
    const int tx = tid & 15;
    const int ty = tid >> 4;
    const int rowTile = blockIdx.x * BM;
    const int colTile = blockIdx.y * BN64;

    const int ar0  = tid >> 2;             // 0..63
    const int ak   = (tid & 3) << 2;       // {0,4,8,12}
    const int aswz = (tid & 3) << 3;       // {0,8,16,24}

    unsigned long long acc[4][4];
    #pragma unroll
    for (int i = 0; i < 4; i++)
        #pragma unroll
        for (int j = 0; j < 4; j++) acc[i][j] = 0ull;

    const float* Xbase  = X + (size_t)(rowTile + ar0) * D + ak;
    const float* Xbase2 = Xbase + (size_t)64 * D;
    const float* Cbase  = C + (size_t)(colTile + ar0) * D + ak;

    float4 pa0 = *(const float4*)(Xbase);
    float4 pa1 = *(const float4*)(Xbase2);
    float4 pb  = *(const float4*)(Cbase);

    for (int kt = 0; kt < D; kt += BK) {
        {
            int ca  = ar0 ^ aswz;
            As[ak + 0][ca] = pa0.x; As[ak + 1][ca] = pa0.y;
            As[ak + 2][ca] = pa0.z; As[ak + 3][ca] = pa0.w;
            int ca2 = (ar0 + 64) ^ aswz;
            As[ak + 0][ca2] = pa1.x; As[ak + 1][ca2] = pa1.y;
            As[ak + 2][ca2] = pa1.z; As[ak + 3][ca2] = pa1.w;
            int cb  = ar0 ^ aswz;
            Bs[ak + 0][cb] = pb.x; Bs[ak + 1][cb] = pb.y;
            Bs[ak + 2][cb] = pb.z; Bs[ak + 3][cb] = pb.w;
        }
        __syncthreads();

        if (kt + BK < D) {
            pa0 = *(const float4*)(Xbase  + kt + BK);
            pa1 = *(const float4*)(Xbase2 + kt + BK);
            pb  = *(const float4*)(Cbase  + kt + BK);
        }

        #pragma unroll
        for (int kk = 0; kk < BK; kk++) {
            const int offs = ((kk >> 2) & 3) << 3;
            const int sa = (ty * 8) ^ offs;
            const int sb = (tx * 4) ^ offs;
            ulonglong2 a01 = *(const ulonglong2*)&As[kk][sa];
            ulonglong2 a23 = *(const ulonglong2*)&As[kk][sa + 4];
            float4 bv = *(const float4*)&Bs[kk][sb];
            unsigned long long b0 = pk2(bv.x), b1 = pk2(bv.y),
                               b2 = pk2(bv.z), b3 = pk2(bv.w);
            unsigned long long A0 = a01.x, A1 = a01.y, A2v = a23.x, A3 = a23.y;
            ffma2(acc[0][0], A0, b0); ffma2(acc[0][1], A0, b1);
            ffma2(acc[0][2], A0, b2); ffma2(acc[0][3], A0, b3);
            ffma2(acc[1][0], A1, b0); ffma2(acc[1][1], A1, b1);
            ffma2(acc[1][2], A1, b2); ffma2(acc[1][3], A1, b3);
            ffma2(acc[2][0], A2v, b0); ffma2(acc[2][1], A2v, b1);
            ffma2(acc[2][2], A2v, b2); ffma2(acc[2][3], A2v, b3);
            ffma2(acc[3][0], A3, b0); ffma2(acc[3][1], A3, b1);
            ffma2(acc[3][2], A3, b2); ffma2(acc[3][3], A3, b3);
        }
        __syncthreads();
    }

    float nrm[4];
    #pragma unroll
    for (int j = 0; j < 4; j++) nrm[j] = norms[colTile + tx * 4 + j];

    if (tid < BM) red[tid] = ~0ull;
    __syncthreads();

    #pragma unroll
    for (int i = 0; i < 4; i++) {
        float lo[4], hi[4];
        #pragma unroll
        for (int j = 0; j < 4; j++) unpk(acc[i][j], lo[j], hi[j]);
        {
            float bs = nrm[0] - 2.f * lo[0];
            int bn = 0;
            #pragma unroll
            for (int j = 1; j < 4; j++) {
                float s = nrm[j] - 2.f * lo[j];
                if (s < bs) { bs = s; bn = j; }
            }
            unsigned long long key =
                ((unsigned long long)fkey(bs) << 32) | (unsigned)(colTile + tx * 4 + bn);
            atomicMin(&red[ty * 8 + 2 * i], key);
        }
        {
            float bs = nrm[0] - 2.f * hi[0];
            int bn = 0;
            #pragma unroll
            for (int j = 1; j < 4; j++) {
                float s = nrm[j] - 2.f * hi[j];
                if (s < bs) { bs = s; bn = j; }
            }
            unsigned long long key =
                ((unsigned long long)fkey(bs) << 32) | (unsigned)(colTile + tx * 4 + bn);
            atomicMin(&red[ty * 8 + 2 * i + 1], key);
        }
    }
    __syncthreads();
    if (tid < BM) atomicMin(&best[rowTile + tid], red[tid]);
}

// ---------------- gather: diff = prev - C[cls]; record cls ----------------
__global__ void gather_kernel(const float* __restrict__ prev, const float* __restrict__ C,
                              const unsigned long long* __restrict__ best,
                              float* __restrict__ outd, int* __restrict__ cls)
{
    int row = blockIdx.x;
    int k = (int)(best[row] & 0xffffffffull);
    if (threadIdx.x == 0) cls[row] = k;
    const float4* pr = (const float4*)(prev + (size_t)row * D);
    const float4* cr = (const float4*)(C + (size_t)k * D);
    float4* orow = (float4*)(outd + (size_t)row * D);
    for (int f = threadIdx.x; f < D / 4; f += blockDim.x) {
        float4 a = pr[f];
        float4 b = cr[f];
        orow[f] = make_float4(a.x - b.x, a.y - b.y, a.z - b.z, a.w - b.w);
    }
}

// ---------------- embed ----------------
__global__ void embed_kernel(const float* __restrict__ e0, const float* __restrict__ e1,
                             const float* __restrict__ e2,
                             const int* __restrict__ cls0, const int* __restrict__ cls1,
                             const int* __restrict__ cls2, float* __restrict__ out)
{
    int b = blockIdx.x;
    int ebase = blockIdx.y * 8;
    __shared__ int s0[NPOS], s1[NPOS], s2[NPOS];
    for (int p = threadIdx.x; p < NPOS; p += blockDim.x) {
        int r = b * NPOS + p;
        s0[p] = cls0[r]; s1[p] = cls1[r]; s2[p] = cls2[r];
    }
    __syncthreads();
    for (int idx = threadIdx.x; idx < 8 * NPOS; idx += blockDim.x) {
        int e = ebase + idx / NPOS;
        int p = idx - (idx / NPOS) * NPOS;
        out[((size_t)b * EMBD + e) * NPOS + p] =
            e0[(size_t)s0[p] * EMBD + e] +
            e1[(size_t)s1[p] * EMBD + e] +
            e2[(size_t)s2[p] * EMBD + e];
    }
}

// ---------------- img_sum ----------------
__global__ void img_kernel(const float* __restrict__ X, const float* __restrict__ Df,
                           float* __restrict__ out)
{
    int b = blockIdx.x, c = blockIdx.y, h = blockIdx.z;
    int w = threadIdx.x;
    int row = b * NPOS + (h >> 4) * 14 + (w >> 4);
    int f = (c << 8) + ((h & 15) << 4) + (w & 15);
    size_t o = (((size_t)b * 3 + c) * 224 + h) * 224 + w;
    size_t s = (size_t)row * D + f;
    out[o] = X[s] - Df[s];
}

// ---------------- diff_out ----------------
__global__ void diffout_kernel(const float* __restrict__ Df, float* __restrict__ out)
{
    int b = blockIdx.x;
    int fbase = blockIdx.y * 8;
    for (int idx = threadIdx.x; idx < 8 * NPOS; idx += blockDim.x) {
        int f = fbase + idx / NPOS;
        int p = idx - (idx / NPOS) * NPOS;
        out[((size_t)b * D + f) * NPOS + p] = Df[((size_t)(b * NPOS + p)) * D + f];
    }
}

// ---------------- launch ----------------
extern "C" void kernel_launch(void* const* d_in, const int* in_sizes, int n_in,
                              void* d_out, int out_size)
{
    const float* data = (const float*)d_in[0];
    const float* c0 = (const float*)d_in[1];
    const float* c1 = (const float*)d_in[2];
    const float* c2 = (const float*)d_in[3];
    const float* e0 = (const float*)d_in[4];
    const float* e1 = (const float*)d_in[5];
    const float* e2 = (const float*)d_in[6];
    float* out = (float*)d_out;

    void *pX, *pD1, *pD2, *pN, *pB, *pC0, *pC1, *pC2;
    cudaGetSymbolAddress(&pX, g_X);
    cudaGetSymbolAddress(&pD1, g_D1);
    cudaGetSymbolAddress(&pD2, g_D2);
    cudaGetSymbolAddress(&pN, g_norms);
    cudaGetSymbolAddress(&pB, g_best);
    cudaGetSymbolAddress(&pC0, g_cls0);
    cudaGetSymbolAddress(&pC1, g_cls1);
    cudaGetSymbolAddress(&pC2, g_cls2);
    float* X  = (float*)pX;
    float* D1 = (float*)pD1;
    float* D2 = (float*)pD2;
    float* nrm = (float*)pN;
    unsigned long long* best = (unsigned long long*)pB;
    int* cls0 = (int*)pC0;
    int* cls1 = (int*)pC1;
    int* cls2 = (int*)pC2;

    patchify_kernel<<<ROWS_TOTAL, 256>>>(data, X);
    norms_kernel<<<NC0, 256>>>(c0, nrm);
    norms_kernel<<<NC1, 256>>>(c1, nrm + NC0);
    norms_kernel<<<NC2, 256>>>(c2, nrm + NC0 + NC1);

    // stage 0 (narrow tile: 392 CTAs -> better per-SM balance)
    init_best_kernel<<<(ROWS_TOTAL + 255) / 256, 256>>>(best);
    score64_kernel<<<dim3(ROWS_TOTAL / BM, NC0 / BN64), 256>>>(X, c0, nrm, best);
    gather_kernel<<<ROWS_TOTAL, 192>>>(X, c0, best, D1, cls0);

    // stage 1
    init_best_kernel<<<(ROWS_TOTAL + 255) / 256, 256>>>(best);
    score_kernel<<<dim3(ROWS_TOTAL / BM, NC1 / BN), 256>>>(D1, c1, nrm + NC0, best);
    gather_kernel<<<ROWS_TOTAL, 192>>>(D1, c1, best, D2, cls1);

    // stage 2
    init_best_kernel<<<(ROWS_TOTAL + 255) / 256, 256>>>(best);
    score_kernel<<<dim3(ROWS_TOTAL / BM, NC2 / BN), 256>>>(D2, c2, nrm + NC0 + NC1, best);
    gather_kernel<<<ROWS_TOTAL, 192>>>(D2, c2, best, D1, cls2);

    // outputs: [embed | img_sum | diff_out]
    embed_kernel<<<dim3(NB, EMBD / 8), 256>>>(e0, e1, e2, cls0, cls1, cls2, out);
    img_kernel<<<dim3(NB, 3, 224), 224>>>(X, D1, out + OUTSLICE);
    diffout_kernel<<<dim3(NB, D / 8), 256>>>(D1, out + 2 * OUTSLICE);
}